// round 2
// baseline (speedup 1.0000x reference)
#include <cuda_runtime.h>
#include <math.h>

#define L_SEQ 256
#define B_SZ  512
#define KIN   15
#define KST   512
#define NLX   1536
#define NTOK  (L_SEQ*B_SZ)   // 131072
#define NB    128            // persistent CTAs (<=148 SMs -> all resident)
#define PAD   34             // smem weight row pad (even -> aligned float2)

// ---------------- scratch (device globals; no allocation) ----------------
__device__ float g_xe[(size_t)NTOK*KST];
__device__ float g_Lx[(size_t)NTOK*NLX];
__device__ float g_states[(size_t)NTOK*KST];
__device__ float g_ty[(size_t)(NTOK-B_SZ)*KST];
__device__ float g_h  [B_SZ*KST];
__device__ float g_hA [B_SZ*KST];
__device__ float g_hB [B_SZ*KST];
__device__ float g_acc[B_SZ*KST];
__device__ float g_zg [B_SZ*KST];
__device__ float g_u  [B_SZ*KST];
__device__ unsigned g_bar_count = 0;
__device__ volatile unsigned g_bar_gen = 0;

__device__ __forceinline__ float sigmoidf_(float x) { return 1.f/(1.f+expf(-x)); }

// software grid barrier (all NB CTAs guaranteed resident: 1 CTA/SM via smem)
__device__ __forceinline__ void grid_sync() {
    __syncthreads();
    if (threadIdx.x == 0) {
        __threadfence();
        unsigned g = g_bar_gen;
        if (atomicAdd(&g_bar_count, 1u) == (unsigned)(NB - 1)) {
            g_bar_count = 0;
            __threadfence();
            g_bar_gen = g + 1u;
        } else {
            while (g_bar_gen == g) { __nanosleep(40); }
            __threadfence();
        }
    }
    __syncthreads();
}

// ---------------- xe = tanh(x @ Win^T + bin) ----------------
__global__ void embed_kernel(const float* __restrict__ seq,
                             const float* __restrict__ Win,
                             const float* __restrict__ bin) {
    int tok = blockIdx.x;
    __shared__ float xs[KIN];
    if (threadIdx.x < KIN) xs[threadIdx.x] = seq[(size_t)tok*16 + threadIdx.x];
    __syncthreads();
    for (int j = threadIdx.x; j < KST; j += blockDim.x) {
        float s = bin[j];
        const float* wr = Win + j*KIN;
        #pragma unroll
        for (int i = 0; i < KIN; i++) s += xs[i]*wr[i];
        g_xe[(size_t)tok*KST + j] = tanhf(s);
    }
}

// ---------------- generic fp32 GEMM: C = act(A[MxK] @ B[NxK]^T) ----------------
template<bool TANH>
__global__ void __launch_bounds__(256) gemm_nt(const float* __restrict__ A,
                                               const float* __restrict__ B,
                                               float* __restrict__ C,
                                               int M, int N, int K) {
    __shared__ float As[16][68];
    __shared__ float Bs[16][68];
    int bm = blockIdx.x*64, bn = blockIdx.y*64;
    int tid = threadIdx.x;
    int tx = tid & 15, ty = tid >> 4;
    int lr = tid >> 2;
    int lc = (tid & 3) << 2;
    float acc[4][4] = {};
    const float* Ap = A + (size_t)(bm+lr)*K + lc;
    const float* Bp = B + (size_t)(bn+lr)*K + lc;
    for (int k0 = 0; k0 < K; k0 += 16) {
        float4 av = *(const float4*)(Ap + k0);
        float4 bv = *(const float4*)(Bp + k0);
        As[lc+0][lr]=av.x; As[lc+1][lr]=av.y; As[lc+2][lr]=av.z; As[lc+3][lr]=av.w;
        Bs[lc+0][lr]=bv.x; Bs[lc+1][lr]=bv.y; Bs[lc+2][lr]=bv.z; Bs[lc+3][lr]=bv.w;
        __syncthreads();
        #pragma unroll
        for (int kk = 0; kk < 16; kk++) {
            float4 a = *(const float4*)&As[kk][ty<<2];
            float4 b = *(const float4*)&Bs[kk][tx<<2];
            acc[0][0]+=a.x*b.x; acc[0][1]+=a.x*b.y; acc[0][2]+=a.x*b.z; acc[0][3]+=a.x*b.w;
            acc[1][0]+=a.y*b.x; acc[1][1]+=a.y*b.y; acc[1][2]+=a.y*b.z; acc[1][3]+=a.y*b.w;
            acc[2][0]+=a.z*b.x; acc[2][1]+=a.z*b.y; acc[2][2]+=a.z*b.z; acc[2][3]+=a.z*b.w;
            acc[3][0]+=a.w*b.x; acc[3][1]+=a.w*b.y; acc[3][2]+=a.w*b.z; acc[3][3]+=a.w*b.w;
        }
        __syncthreads();
    }
    #pragma unroll
    for (int i = 0; i < 4; i++) {
        size_t row = (size_t)(bm + (ty<<2) + i)*N + bn + (tx<<2);
        #pragma unroll
        for (int j = 0; j < 4; j++) {
            float v = acc[i][j];
            if (TANH) v = tanhf(v);
            C[row + j] = v;
        }
    }
}

// ---------------- persistent recurrence kernel ----------------
// 128 CTAs x 256 thr. CTA tile: 64 batch rows x 32 state cols.
// Per stage: phase A = gate GEMM (z,r slabs) -> z, u=r*h ; grid_sync ;
//            phase B = (u)@Wlin^T GEMM + RK4 epilogue ; grid_sync.
// Weights for this CTA's j-tile cached in smem once (3 slabs, [k][j] w/ pad).
__global__ void __launch_bounds__(256) recur_kernel(
    const float* __restrict__ seq, const float* __restrict__ state0,
    const float* __restrict__ Wg, const float* __restrict__ bg,
    const float* __restrict__ Wlin, const float* __restrict__ blin)
{
    extern __shared__ float smem[];
    float* Wz_s = smem;                 // KST*PAD
    float* Wr_s = Wz_s + KST*PAD;
    float* Wl_s = Wr_s + KST*PAD;
    float* As   = Wl_s + KST*PAD;       // 16*68

    int tid = threadIdx.x;
    int b0 = (blockIdx.x & 7) * 64;
    int j0 = (blockIdx.x >> 3) * 32;

    // cache weight slabs ([k][j] layout, coalesced gmem reads)
    for (int idx = tid; idx < 32*KST; idx += 256) {
        int k = idx & (KST-1), jj = idx >> 9;
        Wz_s[k*PAD + jj] = Wg  [(size_t)(j0+jj)*KST       + k];
        Wr_s[k*PAD + jj] = Wg  [(size_t)(KST + j0+jj)*KST + k];
        Wl_s[k*PAD + jj] = Wlin[(size_t)(j0+jj)*KST       + k];
    }
    // init h
    for (int idx = blockIdx.x*256 + tid; idx < B_SZ*KST; idx += NB*256)
        g_h[idx] = state0[idx & (KST-1)];
    grid_sync();

    int tx  = tid & 15;
    int ty4 = (tid >> 4) << 2;
    int lr  = tid >> 2;
    int lc  = (tid & 3) << 2;

    for (int t = 0; t < L_SEQ; ++t) {
        const float* Lxt = g_Lx + (size_t)t*B_SZ*NLX;
        #pragma unroll 1
        for (int s = 1; s <= 4; ++s) {
            const float* hin = (s==1) ? g_h : (s==2 ? g_hA : (s==3 ? g_hB : g_hA));

            // ---- phase A: gates ----
            {
                float az[4][2] = {}, ar[4][2] = {};
                for (int k0 = 0; k0 < KST; k0 += 16) {
                    float4 av = *(const float4*)&hin[(size_t)(b0+lr)*KST + k0 + lc];
                    As[(lc+0)*68 + lr]=av.x; As[(lc+1)*68 + lr]=av.y;
                    As[(lc+2)*68 + lr]=av.z; As[(lc+3)*68 + lr]=av.w;
                    __syncthreads();
                    #pragma unroll
                    for (int kk = 0; kk < 16; kk++) {
                        float4 a  = *(const float4*)&As[kk*68 + ty4];
                        float2 bz = *(const float2*)&Wz_s[(k0+kk)*PAD + (tx<<1)];
                        float2 br = *(const float2*)&Wr_s[(k0+kk)*PAD + (tx<<1)];
                        az[0][0]+=a.x*bz.x; az[0][1]+=a.x*bz.y;
                        az[1][0]+=a.y*bz.x; az[1][1]+=a.y*bz.y;
                        az[2][0]+=a.z*bz.x; az[2][1]+=a.z*bz.y;
                        az[3][0]+=a.w*bz.x; az[3][1]+=a.w*bz.y;
                        ar[0][0]+=a.x*br.x; ar[0][1]+=a.x*br.y;
                        ar[1][0]+=a.y*br.x; ar[1][1]+=a.y*br.y;
                        ar[2][0]+=a.z*br.x; ar[2][1]+=a.z*br.y;
                        ar[3][0]+=a.w*br.x; ar[3][1]+=a.w*br.y;
                    }
                    __syncthreads();
                }
                #pragma unroll
                for (int i = 0; i < 4; i++) {
                    int b = b0 + ty4 + i;
                    const float* lxrow = Lxt + (size_t)b*NLX;
                    #pragma unroll
                    for (int jj = 0; jj < 2; jj++) {
                        int j = j0 + (tx<<1) + jj;
                        size_t idx = (size_t)b*KST + j;
                        float hv = hin[idx];
                        float z = sigmoidf_(lxrow[j]       + az[i][jj] + bg[j]);
                        float r = sigmoidf_(lxrow[KST + j] + ar[i][jj] + bg[KST + j]);
                        g_zg[idx] = z;
                        g_u [idx] = r * hv;
                    }
                }
            }
            grid_sync();

            // ---- phase B: lin GEMM on u + RK4 update ----
            {
                float al[4][2] = {};
                for (int k0 = 0; k0 < KST; k0 += 16) {
                    float4 av = *(const float4*)&g_u[(size_t)(b0+lr)*KST + k0 + lc];
                    As[(lc+0)*68 + lr]=av.x; As[(lc+1)*68 + lr]=av.y;
                    As[(lc+2)*68 + lr]=av.z; As[(lc+3)*68 + lr]=av.w;
                    __syncthreads();
                    #pragma unroll
                    for (int kk = 0; kk < 16; kk++) {
                        float4 a  = *(const float4*)&As[kk*68 + ty4];
                        float2 bl = *(const float2*)&Wl_s[(k0+kk)*PAD + (tx<<1)];
                        al[0][0]+=a.x*bl.x; al[0][1]+=a.x*bl.y;
                        al[1][0]+=a.y*bl.x; al[1][1]+=a.y*bl.y;
                        al[2][0]+=a.z*bl.x; al[2][1]+=a.z*bl.y;
                        al[3][0]+=a.w*bl.x; al[3][1]+=a.w*bl.y;
                    }
                    __syncthreads();
                }
                #pragma unroll
                for (int i = 0; i < 4; i++) {
                    int b = b0 + ty4 + i;
                    float dt = (t > 0) ? seq[((size_t)(t-1)*B_SZ + b)*16 + 15] : 0.f;
                    const float* lxrow = Lxt + (size_t)b*NLX;
                    #pragma unroll
                    for (int jj = 0; jj < 2; jj++) {
                        int j = j0 + (tx<<1) + jj;
                        size_t idx = (size_t)b*KST + j;
                        float hv = hin[idx];
                        float z  = g_zg[idx];
                        float kv = z*(tanhf(lxrow[2*KST + j] + al[i][jj] + blin[j]) - hv);
                        if (s == 1)      { g_acc[idx]  = kv;      g_hA[idx] = g_h[idx] + dt*0.5f*kv; }
                        else if (s == 2) { g_acc[idx] += 2.f*kv;  g_hB[idx] = g_h[idx] + dt*0.5f*kv; }
                        else if (s == 3) { g_acc[idx] += 2.f*kv;  g_hA[idx] = g_h[idx] + dt*kv; }
                        else {
                            float hn = g_h[idx] + dt*(g_acc[idx] + kv)*(1.f/6.f);
                            g_h[idx] = hn;
                            g_states[(size_t)t*B_SZ*KST + idx] = hn;
                        }
                    }
                }
            }
            grid_sync();
        }
    }
}

// ---------------- out[1..255] = g_ty @ Ly2^T ----------------
__global__ void yout_kernel(const float* __restrict__ Ly2, float* __restrict__ out) {
    __shared__ float l2s[8*KST];
    int tid = threadIdx.x;
    for (int i = tid; i < 8*KST; i += 256) l2s[i] = Ly2[i];
    __syncthreads();
    int warp = tid >> 5, lane = tid & 31;
    int tok = blockIdx.x*8 + warp;
    const float* tr = g_ty + (size_t)tok*KST;
    float p[8] = {};
    for (int k = lane; k < KST; k += 32) {
        float tv = tr[k];
        #pragma unroll
        for (int o = 0; o < 8; o++) p[o] += tv*l2s[o*KST + k];
    }
    #pragma unroll
    for (int o = 0; o < 8; o++)
        #pragma unroll
        for (int off = 16; off; off >>= 1)
            p[o] += __shfl_xor_sync(0xffffffffu, p[o], off);
    if (lane == 0) {
        float* op = out + (size_t)(tok + B_SZ)*8;
        #pragma unroll
        for (int o = 0; o < 8; o++) op[o] = p[o];
    }
}

// ---------------- out[0] = Ly(h0) broadcast over batch ----------------
__global__ void y0_kernel(const float* __restrict__ state0,
                          const float* __restrict__ Ly1,
                          const float* __restrict__ Ly2,
                          float* __restrict__ out) {
    __shared__ float h0s[KST];
    __shared__ float tys[KST];
    __shared__ float y0s[8];
    int tid = threadIdx.x;
    for (int j = tid; j < KST; j += 256) h0s[j] = state0[j];
    __syncthreads();
    for (int j = tid; j < KST; j += 256) {
        float s = 0.f;
        const float* lr = Ly1 + (size_t)j*KST;
        for (int k = 0; k < KST; k++) s += h0s[k]*lr[k];
        tys[j] = tanhf(s);
    }
    __syncthreads();
    if (tid < 8) {
        float s = 0.f;
        const float* lr = Ly2 + (size_t)tid*KST;
        for (int k = 0; k < KST; k++) s += tys[k]*lr[k];
        y0s[tid] = s;
    }
    __syncthreads();
    for (int i = tid; i < B_SZ*8; i += 256) out[i] = y0s[i & 7];
}

// ---------------- launch ----------------
extern "C" void kernel_launch(void* const* d_in, const int* in_sizes, int n_in,
                              void* d_out, int out_size) {
    const float* seq    = (const float*)d_in[0];
    const float* state0 = (const float*)d_in[1];
    const float* Win    = (const float*)d_in[2];
    const float* bin    = (const float*)d_in[3];
    const float* Wx     = (const float*)d_in[4];
    const float* Wg     = (const float*)d_in[5];
    const float* bg     = (const float*)d_in[6];
    const float* Wlin   = (const float*)d_in[7];
    const float* blin   = (const float*)d_in[8];
    const float* Ly1    = (const float*)d_in[9];
    const float* Ly2    = (const float*)d_in[10];
    float* out = (float*)d_out;

    float *xe, *Lx, *states, *ty;
    cudaGetSymbolAddress((void**)&xe,     g_xe);
    cudaGetSymbolAddress((void**)&Lx,     g_Lx);
    cudaGetSymbolAddress((void**)&states, g_states);
    cudaGetSymbolAddress((void**)&ty,     g_ty);

    const int smem_bytes = (3*KST*PAD + 16*68) * (int)sizeof(float);  // 213 KB
    cudaFuncSetAttribute(recur_kernel, cudaFuncAttributeMaxDynamicSharedMemorySize, smem_bytes);

    embed_kernel<<<NTOK, 128>>>(seq, Win, bin);
    gemm_nt<false><<<dim3(NTOK/64, NLX/64), 256>>>(xe, Wx, Lx, NTOK, NLX, KST);

    recur_kernel<<<NB, 256, smem_bytes>>>(seq, state0, Wg, bg, Wlin, blin);

    gemm_nt<true><<<dim3((NTOK - B_SZ)/64, KST/64), 256>>>(states, Ly1, ty, NTOK - B_SZ, KST, KST);
    yout_kernel<<<(NTOK - B_SZ)/8, 256>>>(Ly2, out);
    y0_kernel<<<1, 256>>>(state0, Ly1, Ly2, out);
}

// round 3
// speedup vs baseline: 1.0007x; 1.0007x over previous
#include <cuda_runtime.h>
#include <math.h>

#define L_SEQ 256
#define B_SZ  512
#define KIN   15
#define KST   512
#define NLX   1536
#define NTOK  (L_SEQ*B_SZ)   // 131072
#define NB    128            // persistent CTAs (<=148 SMs -> all resident)
#define PAD   34             // smem weight row pad (even -> aligned float2)

// ---------------- scratch (device globals; no allocation) ----------------
__device__ float g_xe[(size_t)NTOK*KST];
__device__ float g_Lx[(size_t)NTOK*NLX];
__device__ float g_states[(size_t)NTOK*KST];
__device__ float g_ty[(size_t)(NTOK-B_SZ)*KST];
__device__ float g_h  [B_SZ*KST];
__device__ float g_hA [B_SZ*KST];
__device__ float g_hB [B_SZ*KST];
__device__ float g_acc[B_SZ*KST];
__device__ float g_zg [B_SZ*KST];
__device__ float g_u  [B_SZ*KST];
__device__ unsigned g_bar_count = 0;
__device__ volatile unsigned g_bar_gen = 0;

__device__ __forceinline__ float sigmoidf_(float x) { return 1.f/(1.f+expf(-x)); }

// software grid barrier (all NB CTAs guaranteed resident: 1 CTA/SM via smem)
__device__ __forceinline__ void grid_sync() {
    __syncthreads();
    if (threadIdx.x == 0) {
        __threadfence();
        unsigned g = g_bar_gen;
        if (atomicAdd(&g_bar_count, 1u) == (unsigned)(NB - 1)) {
            g_bar_count = 0;
            __threadfence();
            g_bar_gen = g + 1u;
        } else {
            while (g_bar_gen == g) { __nanosleep(40); }
            __threadfence();
        }
    }
    __syncthreads();
}

// ---------------- xe = tanh(x @ Win^T + bin) ----------------
__global__ void embed_kernel(const float* __restrict__ seq,
                             const float* __restrict__ Win,
                             const float* __restrict__ bin) {
    int tok = blockIdx.x;
    __shared__ float xs[KIN];
    if (threadIdx.x < KIN) xs[threadIdx.x] = seq[(size_t)tok*16 + threadIdx.x];
    __syncthreads();
    for (int j = threadIdx.x; j < KST; j += blockDim.x) {
        float s = bin[j];
        const float* wr = Win + j*KIN;
        #pragma unroll
        for (int i = 0; i < KIN; i++) s += xs[i]*wr[i];
        g_xe[(size_t)tok*KST + j] = tanhf(s);
    }
}

// ---------------- generic fp32 GEMM: C = act(A[MxK] @ B[NxK]^T) ----------------
template<bool TANH>
__global__ void __launch_bounds__(256) gemm_nt(const float* __restrict__ A,
                                               const float* __restrict__ B,
                                               float* __restrict__ C,
                                               int M, int N, int K) {
    __shared__ float As[16][68];
    __shared__ float Bs[16][68];
    int bm = blockIdx.x*64, bn = blockIdx.y*64;
    int tid = threadIdx.x;
    int tx = tid & 15, ty = tid >> 4;
    int lr = tid >> 2;
    int lc = (tid & 3) << 2;
    float acc[4][4] = {};
    const float* Ap = A + (size_t)(bm+lr)*K + lc;
    const float* Bp = B + (size_t)(bn+lr)*K + lc;
    for (int k0 = 0; k0 < K; k0 += 16) {
        float4 av = *(const float4*)(Ap + k0);
        float4 bv = *(const float4*)(Bp + k0);
        As[lc+0][lr]=av.x; As[lc+1][lr]=av.y; As[lc+2][lr]=av.z; As[lc+3][lr]=av.w;
        Bs[lc+0][lr]=bv.x; Bs[lc+1][lr]=bv.y; Bs[lc+2][lr]=bv.z; Bs[lc+3][lr]=bv.w;
        __syncthreads();
        #pragma unroll
        for (int kk = 0; kk < 16; kk++) {
            float4 a = *(const float4*)&As[kk][ty<<2];
            float4 b = *(const float4*)&Bs[kk][tx<<2];
            acc[0][0]+=a.x*b.x; acc[0][1]+=a.x*b.y; acc[0][2]+=a.x*b.z; acc[0][3]+=a.x*b.w;
            acc[1][0]+=a.y*b.x; acc[1][1]+=a.y*b.y; acc[1][2]+=a.y*b.z; acc[1][3]+=a.y*b.w;
            acc[2][0]+=a.z*b.x; acc[2][1]+=a.z*b.y; acc[2][2]+=a.z*b.z; acc[2][3]+=a.z*b.w;
            acc[3][0]+=a.w*b.x; acc[3][1]+=a.w*b.y; acc[3][2]+=a.w*b.z; acc[3][3]+=a.w*b.w;
        }
        __syncthreads();
    }
    #pragma unroll
    for (int i = 0; i < 4; i++) {
        size_t row = (size_t)(bm + (ty<<2) + i)*N + bn + (tx<<2);
        #pragma unroll
        for (int j = 0; j < 4; j++) {
            float v = acc[i][j];
            if (TANH) v = tanhf(v);
            C[row + j] = v;
        }
    }
}

// ---------------- persistent recurrence kernel ----------------
// 128 CTAs x 256 thr. CTA tile: 64 batch rows x 32 state cols.
// Per stage: phase A = gate GEMM (z,r slabs) -> z, u=r*h ; grid_sync ;
//            phase B = (u)@Wlin^T GEMM + RK4 epilogue ; grid_sync.
// Weights for this CTA's j-tile cached in smem once (3 slabs, [k][j] w/ pad).
__global__ void __launch_bounds__(256) recur_kernel(
    const float* __restrict__ seq, const float* __restrict__ state0,
    const float* __restrict__ Wg, const float* __restrict__ bg,
    const float* __restrict__ Wlin, const float* __restrict__ blin)
{
    extern __shared__ float smem[];
    float* Wz_s = smem;                 // KST*PAD
    float* Wr_s = Wz_s + KST*PAD;
    float* Wl_s = Wr_s + KST*PAD;
    float* As   = Wl_s + KST*PAD;       // 16*68

    int tid = threadIdx.x;
    int b0 = (blockIdx.x & 7) * 64;
    int j0 = (blockIdx.x >> 3) * 32;

    // cache weight slabs ([k][j] layout, coalesced gmem reads)
    for (int idx = tid; idx < 32*KST; idx += 256) {
        int k = idx & (KST-1), jj = idx >> 9;
        Wz_s[k*PAD + jj] = Wg  [(size_t)(j0+jj)*KST       + k];
        Wr_s[k*PAD + jj] = Wg  [(size_t)(KST + j0+jj)*KST + k];
        Wl_s[k*PAD + jj] = Wlin[(size_t)(j0+jj)*KST       + k];
    }
    // init h
    for (int idx = blockIdx.x*256 + tid; idx < B_SZ*KST; idx += NB*256)
        g_h[idx] = state0[idx & (KST-1)];
    grid_sync();

    int tx  = tid & 15;
    int ty4 = (tid >> 4) << 2;
    int lr  = tid >> 2;
    int lc  = (tid & 3) << 2;

    for (int t = 0; t < L_SEQ; ++t) {
        const float* Lxt = g_Lx + (size_t)t*B_SZ*NLX;
        #pragma unroll 1
        for (int s = 1; s <= 4; ++s) {
            const float* hin = (s==1) ? g_h : (s==2 ? g_hA : (s==3 ? g_hB : g_hA));

            // ---- phase A: gates ----
            {
                float az[4][2] = {}, ar[4][2] = {};
                for (int k0 = 0; k0 < KST; k0 += 16) {
                    float4 av = *(const float4*)&hin[(size_t)(b0+lr)*KST + k0 + lc];
                    As[(lc+0)*68 + lr]=av.x; As[(lc+1)*68 + lr]=av.y;
                    As[(lc+2)*68 + lr]=av.z; As[(lc+3)*68 + lr]=av.w;
                    __syncthreads();
                    #pragma unroll
                    for (int kk = 0; kk < 16; kk++) {
                        float4 a  = *(const float4*)&As[kk*68 + ty4];
                        float2 bz = *(const float2*)&Wz_s[(k0+kk)*PAD + (tx<<1)];
                        float2 br = *(const float2*)&Wr_s[(k0+kk)*PAD + (tx<<1)];
                        az[0][0]+=a.x*bz.x; az[0][1]+=a.x*bz.y;
                        az[1][0]+=a.y*bz.x; az[1][1]+=a.y*bz.y;
                        az[2][0]+=a.z*bz.x; az[2][1]+=a.z*bz.y;
                        az[3][0]+=a.w*bz.x; az[3][1]+=a.w*bz.y;
                        ar[0][0]+=a.x*br.x; ar[0][1]+=a.x*br.y;
                        ar[1][0]+=a.y*br.x; ar[1][1]+=a.y*br.y;
                        ar[2][0]+=a.z*br.x; ar[2][1]+=a.z*br.y;
                        ar[3][0]+=a.w*br.x; ar[3][1]+=a.w*br.y;
                    }
                    __syncthreads();
                }
                #pragma unroll
                for (int i = 0; i < 4; i++) {
                    int b = b0 + ty4 + i;
                    const float* lxrow = Lxt + (size_t)b*NLX;
                    #pragma unroll
                    for (int jj = 0; jj < 2; jj++) {
                        int j = j0 + (tx<<1) + jj;
                        size_t idx = (size_t)b*KST + j;
                        float hv = hin[idx];
                        float z = sigmoidf_(lxrow[j]       + az[i][jj] + bg[j]);
                        float r = sigmoidf_(lxrow[KST + j] + ar[i][jj] + bg[KST + j]);
                        g_zg[idx] = z;
                        g_u [idx] = r * hv;
                    }
                }
            }
            grid_sync();

            // ---- phase B: lin GEMM on u + RK4 update ----
            {
                float al[4][2] = {};
                for (int k0 = 0; k0 < KST; k0 += 16) {
                    float4 av = *(const float4*)&g_u[(size_t)(b0+lr)*KST + k0 + lc];
                    As[(lc+0)*68 + lr]=av.x; As[(lc+1)*68 + lr]=av.y;
                    As[(lc+2)*68 + lr]=av.z; As[(lc+3)*68 + lr]=av.w;
                    __syncthreads();
                    #pragma unroll
                    for (int kk = 0; kk < 16; kk++) {
                        float4 a  = *(const float4*)&As[kk*68 + ty4];
                        float2 bl = *(const float2*)&Wl_s[(k0+kk)*PAD + (tx<<1)];
                        al[0][0]+=a.x*bl.x; al[0][1]+=a.x*bl.y;
                        al[1][0]+=a.y*bl.x; al[1][1]+=a.y*bl.y;
                        al[2][0]+=a.z*bl.x; al[2][1]+=a.z*bl.y;
                        al[3][0]+=a.w*bl.x; al[3][1]+=a.w*bl.y;
                    }
                    __syncthreads();
                }
                #pragma unroll
                for (int i = 0; i < 4; i++) {
                    int b = b0 + ty4 + i;
                    float dt = (t > 0) ? seq[((size_t)(t-1)*B_SZ + b)*16 + 15] : 0.f;
                    const float* lxrow = Lxt + (size_t)b*NLX;
                    #pragma unroll
                    for (int jj = 0; jj < 2; jj++) {
                        int j = j0 + (tx<<1) + jj;
                        size_t idx = (size_t)b*KST + j;
                        float hv = hin[idx];
                        float z  = g_zg[idx];
                        float kv = z*(tanhf(lxrow[2*KST + j] + al[i][jj] + blin[j]) - hv);
                        if (s == 1)      { g_acc[idx]  = kv;      g_hA[idx] = g_h[idx] + dt*0.5f*kv; }
                        else if (s == 2) { g_acc[idx] += 2.f*kv;  g_hB[idx] = g_h[idx] + dt*0.5f*kv; }
                        else if (s == 3) { g_acc[idx] += 2.f*kv;  g_hA[idx] = g_h[idx] + dt*kv; }
                        else {
                            float hn = g_h[idx] + dt*(g_acc[idx] + kv)*(1.f/6.f);
                            g_h[idx] = hn;
                            g_states[(size_t)t*B_SZ*KST + idx] = hn;
                        }
                    }
                }
            }
            grid_sync();
        }
    }
}

// ---------------- out[1..255] = g_ty @ Ly2^T ----------------
__global__ void yout_kernel(const float* __restrict__ Ly2, float* __restrict__ out) {
    __shared__ float l2s[8*KST];
    int tid = threadIdx.x;
    for (int i = tid; i < 8*KST; i += 256) l2s[i] = Ly2[i];
    __syncthreads();
    int warp = tid >> 5, lane = tid & 31;
    int tok = blockIdx.x*8 + warp;
    const float* tr = g_ty + (size_t)tok*KST;
    float p[8] = {};
    for (int k = lane; k < KST; k += 32) {
        float tv = tr[k];
        #pragma unroll
        for (int o = 0; o < 8; o++) p[o] += tv*l2s[o*KST + k];
    }
    #pragma unroll
    for (int o = 0; o < 8; o++)
        #pragma unroll
        for (int off = 16; off; off >>= 1)
            p[o] += __shfl_xor_sync(0xffffffffu, p[o], off);
    if (lane == 0) {
        float* op = out + (size_t)(tok + B_SZ)*8;
        #pragma unroll
        for (int o = 0; o < 8; o++) op[o] = p[o];
    }
}

// ---------------- out[0] = Ly(h0) broadcast over batch ----------------
__global__ void y0_kernel(const float* __restrict__ state0,
                          const float* __restrict__ Ly1,
                          const float* __restrict__ Ly2,
                          float* __restrict__ out) {
    __shared__ float h0s[KST];
    __shared__ float tys[KST];
    __shared__ float y0s[8];
    int tid = threadIdx.x;
    for (int j = tid; j < KST; j += 256) h0s[j] = state0[j];
    __syncthreads();
    for (int j = tid; j < KST; j += 256) {
        float s = 0.f;
        const float* lr = Ly1 + (size_t)j*KST;
        for (int k = 0; k < KST; k++) s += h0s[k]*lr[k];
        tys[j] = tanhf(s);
    }
    __syncthreads();
    if (tid < 8) {
        float s = 0.f;
        const float* lr = Ly2 + (size_t)tid*KST;
        for (int k = 0; k < KST; k++) s += tys[k]*lr[k];
        y0s[tid] = s;
    }
    __syncthreads();
    for (int i = tid; i < B_SZ*8; i += 256) out[i] = y0s[i & 7];
}

// ---------------- launch ----------------
extern "C" void kernel_launch(void* const* d_in, const int* in_sizes, int n_in,
                              void* d_out, int out_size) {
    const float* seq    = (const float*)d_in[0];
    const float* state0 = (const float*)d_in[1];
    const float* Win    = (const float*)d_in[2];
    const float* bin    = (const float*)d_in[3];
    const float* Wx     = (const float*)d_in[4];
    const float* Wg     = (const float*)d_in[5];
    const float* bg     = (const float*)d_in[6];
    const float* Wlin   = (const float*)d_in[7];
    const float* blin   = (const float*)d_in[8];
    const float* Ly1    = (const float*)d_in[9];
    const float* Ly2    = (const float*)d_in[10];
    float* out = (float*)d_out;

    float *xe, *Lx, *states, *ty;
    cudaGetSymbolAddress((void**)&xe,     g_xe);
    cudaGetSymbolAddress((void**)&Lx,     g_Lx);
    cudaGetSymbolAddress((void**)&states, g_states);
    cudaGetSymbolAddress((void**)&ty,     g_ty);

    const int smem_bytes = (3*KST*PAD + 16*68) * (int)sizeof(float);  // 213 KB
    cudaFuncSetAttribute(recur_kernel, cudaFuncAttributeMaxDynamicSharedMemorySize, smem_bytes);

    embed_kernel<<<NTOK, 128>>>(seq, Win, bin);
    gemm_nt<false><<<dim3(NTOK/64, NLX/64), 256>>>(xe, Wx, Lx, NTOK, NLX, KST);

    recur_kernel<<<NB, 256, smem_bytes>>>(seq, state0, Wg, bg, Wlin, blin);

    gemm_nt<true><<<dim3((NTOK - B_SZ)/64, KST/64), 256>>>(states, Ly1, ty, NTOK - B_SZ, KST, KST);
    yout_kernel<<<(NTOK - B_SZ)/8, 256>>>(Ly2, out);
    y0_kernel<<<1, 256>>>(state0, Ly1, Ly2, out);
}